// round 3
// baseline (speedup 1.0000x reference)
#include <cuda_runtime.h>
#include <math.h>
#include <stdint.h>

// FIRE bias: out[1, H=12, S=2048, S=2048] fp32.
// bias[h,s,t] = b2[h] + sum_w w2[h,w] * relu(nd*w1[w] + b1[w])
// nd[s,t] = log(|s-t|+eps)*c ... precisely:
//   lr[d]  = log((|d|+EPS)*c + LOG_BIAS + EPS)
//   ln[s]  = log(|c*(max(s,thr)+EPS)| + LOG_BIAS + EPS),  thr = |L_mult*init_L|
//   nd     = lr[|s-t|] / ln[s]
// The head MLP is piecewise-linear in nd with 32 hinges at -b1[w]/w1[w].
// Setup kernel builds per-segment (alpha,beta) per head; main kernel does a
// binary search over sorted hinges + 1 FMA per head per element.

#define S_LEN 2048
#define H_HEADS 12
#define W_HID 32
#define N_SEG 33            // W_HID + 1
#define EPSF 1e-6f
#define LOG_BIAS_EPS (1.0f + 1e-6f)

__device__ float  g_lr[S_LEN];          // log_rel table by distance d
__device__ float  g_invln[S_LEN];       // 1/log_norm per row s
__device__ float  g_hinge[W_HID];       // sorted hinge values
__device__ float2 g_ab[N_SEG * H_HEADS]; // (alpha, beta) per (segment, head)

__global__ void fire_setup_kernel(const float* __restrict__ w1,
                                  const float* __restrict__ b1,
                                  const float* __restrict__ w2,
                                  const float* __restrict__ b2,
                                  const float* __restrict__ pc,
                                  const float* __restrict__ pLm,
                                  const float* __restrict__ pL0)
{
    __shared__ float s_w1[W_HID], s_b1[W_HID], s_h[W_HID], s_sorted[W_HID];
    __shared__ int   s_rank[W_HID];

    const int tid = threadIdx.x;
    const float c   = *pc;
    const float thr = fabsf((*pLm) * (*pL0));

    if (tid < W_HID) { s_w1[tid] = w1[tid]; s_b1[tid] = b1[tid]; }
    __syncthreads();

    if (tid < W_HID) {
        float w = s_w1[tid];
        // w1==0: relu term is constant; push hinge to +inf so it never counts
        // in the runtime rank search.
        float h = (w != 0.0f) ? (-s_b1[tid] / w) : __int_as_float(0x7f800000);
        s_h[tid] = h;
    }
    __syncthreads();

    if (tid < W_HID) {
        float h = s_h[tid];
        int r = 0;
        #pragma unroll
        for (int j = 0; j < W_HID; ++j) {
            float hj = s_h[j];
            r += (hj < h) || (hj == h && j < tid);   // stable rank (0-based)
        }
        s_rank[tid]   = r;
        s_sorted[r]   = h;
    }
    __syncthreads();

    if (tid < W_HID) g_hinge[tid] = s_sorted[tid];

    // distance / row tables
    for (int i = tid; i < S_LEN; i += blockDim.x) {
        float ar = fabsf((float)i) + EPSF;
        g_lr[i] = logf(ar * c + LOG_BIAS_EPS);
        float pn = fmaxf((float)i, thr) + EPSF;
        g_invln[i] = 1.0f / logf(fabsf(c * pn) + LOG_BIAS_EPS);
    }

    // per-segment linear coefficients. Segment k = {nd : rank(nd) == k},
    // rank(nd) = #sorted hinges <= nd, k in [0, 32].
    // w active on segment k:  w1>0 -> rank_w < k ;  w1<0 -> rank_w >= k ;
    // w1==0 -> b1>0 (constant).
    for (int id = tid; id < N_SEG * H_HEADS; id += blockDim.x) {
        int k = id / H_HEADS;
        int h = id % H_HEADS;
        float a = 0.0f;
        float b = b2[h];
        #pragma unroll
        for (int w = 0; w < W_HID; ++w) {
            float ww = s_w1[w];
            bool act;
            if (ww > 0.0f)       act = (s_rank[w] <  k);
            else if (ww < 0.0f)  act = (s_rank[w] >= k);
            else                 act = (s_b1[w] > 0.0f);
            if (act) {
                float wv = w2[h * W_HID + w];
                a = fmaf(wv, ww,      a);
                b = fmaf(wv, s_b1[w], b);
            }
        }
        g_ab[k * H_HEADS + h] = make_float2(a, b);
    }
}

__device__ __forceinline__ int seg_search(const float* __restrict__ sh_h, float nd)
{
    // rank = number of sorted hinges <= nd, in [0, 32]
    int k = 0;
    if (sh_h[k + 15] <= nd) k += 16;
    if (sh_h[k + 7]  <= nd) k += 8;
    if (sh_h[k + 3]  <= nd) k += 4;
    if (sh_h[k + 1]  <= nd) k += 2;
    if (sh_h[k]      <= nd) k += 1;
    if (k == 31 && sh_h[31] <= nd) k += 1;   // rank 32: all hinges <= nd
    return k;
}

__global__ __launch_bounds__(256)
void fire_main_kernel(float* __restrict__ out)
{
    __shared__ float  sh_h[W_HID];
    __shared__ float2 sh_ab[N_SEG * H_HEADS];

    const int tid = threadIdx.x;
    if (tid < W_HID) sh_h[tid] = g_hinge[tid];
    for (int i = tid; i < N_SEG * H_HEADS; i += 256) sh_ab[i] = g_ab[i];
    __syncthreads();

    const int s  = blockIdx.y;
    const int t0 = (blockIdx.x * 256 + tid) * 4;

    const float invln = __ldg(&g_invln[s]);

    float nd0, nd1, nd2, nd3;
    {
        int d0 = abs(s - (t0 + 0));
        int d1 = abs(s - (t0 + 1));
        int d2 = abs(s - (t0 + 2));
        int d3 = abs(s - (t0 + 3));
        nd0 = __ldg(&g_lr[d0]) * invln;
        nd1 = __ldg(&g_lr[d1]) * invln;
        nd2 = __ldg(&g_lr[d2]) * invln;
        nd3 = __ldg(&g_lr[d3]) * invln;
    }

    int k0 = seg_search(sh_h, nd0);
    int k1 = seg_search(sh_h, nd1);
    int k2 = seg_search(sh_h, nd2);
    int k3 = seg_search(sh_h, nd3);

    const size_t plane = (size_t)S_LEN * S_LEN;
    const size_t base  = (size_t)s * S_LEN + t0;

    bool uni = __all_sync(0xffffffffu, (k0 == k1) & (k1 == k2) & (k2 == k3));

    if (uni) {
        const float2* __restrict__ row = &sh_ab[k0 * H_HEADS];
        #pragma unroll
        for (int h = 0; h < H_HEADS; ++h) {
            float2 ab = row[h];
            float4 v;
            v.x = fmaf(ab.x, nd0, ab.y);
            v.y = fmaf(ab.x, nd1, ab.y);
            v.z = fmaf(ab.x, nd2, ab.y);
            v.w = fmaf(ab.x, nd3, ab.y);
            *reinterpret_cast<float4*>(out + (size_t)h * plane + base) = v;
        }
    } else {
        const float2* __restrict__ r0 = &sh_ab[k0 * H_HEADS];
        const float2* __restrict__ r1 = &sh_ab[k1 * H_HEADS];
        const float2* __restrict__ r2 = &sh_ab[k2 * H_HEADS];
        const float2* __restrict__ r3 = &sh_ab[k3 * H_HEADS];
        #pragma unroll
        for (int h = 0; h < H_HEADS; ++h) {
            float2 a0 = r0[h], a1 = r1[h], a2 = r2[h], a3 = r3[h];
            float4 v;
            v.x = fmaf(a0.x, nd0, a0.y);
            v.y = fmaf(a1.x, nd1, a1.y);
            v.z = fmaf(a2.x, nd2, a2.y);
            v.w = fmaf(a3.x, nd3, a3.y);
            *reinterpret_cast<float4*>(out + (size_t)h * plane + base) = v;
        }
    }
}

extern "C" void kernel_launch(void* const* d_in, const int* in_sizes, int n_in,
                              void* d_out, int out_size)
{
    // inputs (metadata order): x, w1, b1, w2, b2, c, L_multiplier, init_L
    const float* w1 = (const float*)d_in[1];
    const float* b1 = (const float*)d_in[2];
    const float* w2 = (const float*)d_in[3];
    const float* b2 = (const float*)d_in[4];
    const float* c  = (const float*)d_in[5];
    const float* Lm = (const float*)d_in[6];
    const float* L0 = (const float*)d_in[7];
    float* out = (float*)d_out;

    fire_setup_kernel<<<1, 512>>>(w1, b1, w2, b2, c, Lm, L0);

    dim3 grid(S_LEN / (256 * 4), S_LEN);   // (2, 2048)
    fire_main_kernel<<<grid, 256>>>(out);
}